// round 2
// baseline (speedup 1.0000x reference)
#include <cuda_runtime.h>
#include <math.h>

#define BV 48
#define BT 48
#define MW 32
#define NT 196
#define CD 512
#define HIDN 102
#define NKEEP 98
#define NSEL 39
#define NTOKS 41
#define NPAIR (BT*BV)
#define RTOT (NPAIR*NKEEP)

// ---------------- scratch (device globals; no allocations allowed) ----------
__device__ float g_capn[BT*MW*CD];          // normalized captions
__device__ float g_spn[BV*NT*CD];           // normalized spatial tokens
__device__ float g_glo[BV*CD];              // l2norm(mean(spatial))
__device__ float g_sim[BV*NT];              // s_im
__device__ float g_score[NPAIR*NT];         // s_im + attn_y
__device__ int   g_keep[NPAIR*NKEEP];       // kept token indices (sorted desc)
__device__ float g_extra[NPAIR*CD];         // softmax-pooled non-kept token
__device__ float g_mu[NPAIR*NKEEP];
__device__ float g_rstd[NPAIR*NKEEP];
__device__ float g_h[(size_t)RTOT*HIDN];    // gelu(LN(sel)@w1+b1)
__device__ float g_logits[(size_t)RTOT*NSEL];

__device__ __forceinline__ float warpSum(float v){
  #pragma unroll
  for (int o=16;o;o>>=1) v += __shfl_xor_sync(0xffffffffu, v, o);
  return v;
}
__device__ __forceinline__ float warpMax(float v){
  #pragma unroll
  for (int o=16;o;o>>=1) v = fmaxf(v, __shfl_xor_sync(0xffffffffu, v, o));
  return v;
}

// ------------------------- caption row l2norm -------------------------------
__global__ void k_capnorm(const float* __restrict__ cap){
  int row = blockIdx.x;                 // 0..1535
  int tid = threadIdx.x;                // 128
  const float4* src = (const float4*)(cap + (size_t)row*CD);
  float4 v = src[tid];
  float ss = v.x*v.x + v.y*v.y + v.z*v.z + v.w*v.w;
  ss = warpSum(ss);
  __shared__ float rs[4]; __shared__ float s_inv;
  if ((tid&31)==0) rs[tid>>5] = ss;
  __syncthreads();
  if (tid==0){ float s = rs[0]+rs[1]+rs[2]+rs[3]; s_inv = 1.0f/fmaxf(sqrtf(s), 1e-12f); }
  __syncthreads();
  float inv = s_inv;
  float4 o = make_float4(v.x*inv, v.y*inv, v.z*inv, v.w*inv);
  ((float4*)(g_capn + (size_t)row*CD))[tid] = o;
}

// ------------------------- spatial row l2norm -------------------------------
__global__ void k_spnorm(const float* __restrict__ img){
  int row = blockIdx.x;                 // 0..9407  (b*196+n)
  int b = row / NT, n = row % NT;
  int tid = threadIdx.x;                // 128
  const float4* src = (const float4*)(img + ((size_t)(b*(NT+1) + 1 + n))*CD);
  float4 v = src[tid];
  float ss = v.x*v.x + v.y*v.y + v.z*v.z + v.w*v.w;
  ss = warpSum(ss);
  __shared__ float rs[4]; __shared__ float s_inv;
  if ((tid&31)==0) rs[tid>>5] = ss;
  __syncthreads();
  if (tid==0){ float s = rs[0]+rs[1]+rs[2]+rs[3]; s_inv = 1.0f/fmaxf(sqrtf(s), 1e-12f); }
  __syncthreads();
  float inv = s_inv;
  float4 o = make_float4(v.x*inv, v.y*inv, v.z*inv, v.w*inv);
  ((float4*)(g_spn + (size_t)row*CD))[tid] = o;
}

// ------------------- glo = l2norm(mean over tokens) -------------------------
__global__ void k_glo(const float* __restrict__ img){
  int b = blockIdx.x; int tid = threadIdx.x;   // 256 threads
  float a0 = 0.f, a1 = 0.f;
  for (int n = 0; n < NT; n++){
    const float* r = img + ((size_t)(b*(NT+1) + 1 + n))*CD;
    a0 += r[tid]; a1 += r[tid+256];
  }
  a0 *= (1.0f/NT); a1 *= (1.0f/NT);
  float ss = a0*a0 + a1*a1;
  ss = warpSum(ss);
  __shared__ float rs[8]; __shared__ float s_inv;
  if ((tid&31)==0) rs[tid>>5] = ss;
  __syncthreads();
  if (tid==0){ float s=0.f; for (int i=0;i<8;i++) s += rs[i]; s_inv = 1.0f/fmaxf(sqrtf(s),1e-12f); }
  __syncthreads();
  float inv = s_inv;
  g_glo[b*CD + tid]       = a0*inv;
  g_glo[b*CD + tid + 256] = a1*inv;
}

// ------------------- s_im = dot(glo[b], spn[b,n]) ----------------------------
__global__ void k_sim(){
  int b = blockIdx.x; int tid = threadIdx.x;
  int wid = tid >> 5, lane = tid & 31;
  __shared__ float sg[CD];
  sg[tid] = g_glo[b*CD + tid]; sg[tid+256] = g_glo[b*CD + tid + 256];
  __syncthreads();
  const float4* g4 = (const float4*)sg;
  for (int n = wid; n < NT; n += 8){
    const float4* sp = (const float4*)(g_spn + ((size_t)(b*NT + n))*CD);
    float d = 0.f;
    #pragma unroll
    for (int i=0;i<4;i++){
      float4 a = sp[lane + i*32]; float4 c = g4[lane + i*32];
      d += a.x*c.x + a.y*c.y + a.z*c.z + a.w*c.w;
    }
    d = warpSum(d);
    if (lane==0) g_sim[b*NT + n] = d;
  }
}

// ---------- score[j,b,n] = s_im[b,n] + max_m dot(capn[j,m], spn[b,n]) --------
#define CAP_STRIDE 516
#define SCORE_SMEM ((32*CAP_STRIDE + 8*512)*4)
__global__ void k_score(){
  extern __shared__ float sm[];
  float* capsh = sm;                       // 32 x 516
  float* svbuf = sm + 32*CAP_STRIDE;       // 8 x 512
  int jb = blockIdx.x;                     // j*48 + b
  int j = jb / BV, b = jb % BV;
  int tid = threadIdx.x;
  for (int f = tid; f < MW*CD; f += 256){
    int r = f >> 9, c = f & 511;
    capsh[r*CAP_STRIDE + c] = g_capn[(size_t)j*MW*CD + f];
  }
  __syncthreads();
  int wid = tid >> 5, lane = tid & 31;
  float4* sv4 = (float4*)(svbuf + wid*512);
  const float4* c4 = (const float4*)(capsh + lane*CAP_STRIDE);
  for (int n = wid; n < NT; n += 8){
    const float4* sp = (const float4*)(g_spn + ((size_t)(b*NT + n))*CD);
    #pragma unroll
    for (int i=0;i<4;i++) sv4[lane + i*32] = sp[lane + i*32];
    __syncwarp();
    float acc = 0.f;
    #pragma unroll 8
    for (int i=0;i<128;i++){
      float4 a = c4[i]; float4 s = sv4[i];
      acc += a.x*s.x + a.y*s.y + a.z*s.z + a.w*s.w;
    }
    float mx = warpMax(acc);
    if (lane==0) g_score[(size_t)jb*NT + n] = g_sim[b*NT + n] + mx;
    __syncwarp();
  }
}

// ---- per (j,b): bitonic sort scores desc, keep idx, extra token, LN stats ---
__global__ void k_sort(const float* __restrict__ img){
  __shared__ float vals[256];
  __shared__ int   idxs[256];
  __shared__ float wbuf[NKEEP];
  __shared__ float rs[8]; __shared__ float s_tot;
  int jb = blockIdx.x; int b = jb % BV;
  int tid = threadIdx.x;
  vals[tid] = (tid < NT) ? -g_score[(size_t)jb*NT + tid] : 3.4e38f;
  idxs[tid] = tid;
  __syncthreads();
  // bitonic ascending on (-score) == descending on score
  for (int k = 2; k <= 256; k <<= 1){
    for (int s = k >> 1; s > 0; s >>= 1){
      int ixj = tid ^ s;
      if (ixj > tid){
        bool up = ((tid & k) == 0);
        float v1 = vals[tid], v2 = vals[ixj];
        if ((v1 > v2) == up){
          vals[tid] = v2; vals[ixj] = v1;
          int t = idxs[tid]; idxs[tid] = idxs[ixj]; idxs[ixj] = t;
        }
      }
      __syncthreads();
    }
  }
  if (tid < NKEEP) g_keep[(size_t)jb*NKEEP + tid] = idxs[tid];
  // softmax over tail (sorted positions 98..195); scores = -vals
  float e = 0.f;
  if (tid < NKEEP){ e = expf(vals[NKEEP] - vals[NKEEP + tid]); wbuf[tid] = e; }
  float v = warpSum(e);
  if ((tid&31)==0) rs[tid>>5] = v;
  __syncthreads();
  if (tid==0){ float s=0.f; for (int i=0;i<8;i++) s += rs[i]; s_tot = s; }
  __syncthreads();
  float inv = 1.0f / s_tot;
  // extra token = weighted sum of non-kept raw spatial rows
  {
    float a0 = 0.f, a1 = 0.f;
    for (int i = 0; i < NKEEP; i++){
      float w = wbuf[i];
      const float* r = img + ((size_t)(b*(NT+1) + 1 + idxs[NKEEP+i]))*CD;
      a0 += w * r[tid]; a1 += w * r[tid+256];
    }
    g_extra[(size_t)jb*CD + tid]       = a0*inv;
    g_extra[(size_t)jb*CD + tid + 256] = a1*inv;
  }
  // LN stats of kept rows
  int wid = tid >> 5, lane = tid & 31;
  for (int r = wid; r < NKEEP; r += 8){
    int tok = idxs[r];
    const float4* p = (const float4*)(img + ((size_t)(b*(NT+1) + 1 + tok))*CD);
    float s = 0.f, ss = 0.f;
    #pragma unroll
    for (int i=0;i<4;i++){
      float4 x = p[lane + i*32];
      s  += x.x + x.y + x.z + x.w;
      ss += x.x*x.x + x.y*x.y + x.z*x.z + x.w*x.w;
    }
    s = warpSum(s); ss = warpSum(ss);
    if (lane==0){
      float mu = s * (1.0f/CD);
      float var = ss * (1.0f/CD) - mu*mu;
      g_mu[(size_t)jb*NKEEP + r]   = mu;
      g_rstd[(size_t)jb*NKEEP + r] = rsqrtf(var + 1e-5f);
    }
  }
}

// -------- GEMM1: H = gelu( LN(gathered sel) @ w1 + b1 ), 225792 x 102 --------
__global__ void k_mlp1(const float* __restrict__ img,
                       const float* __restrict__ lng, const float* __restrict__ lnb,
                       const float* __restrict__ w1,  const float* __restrict__ b1){
  __shared__ float As[32][68];
  __shared__ float Bs[32][68];
  __shared__ int   sIdx[64];
  __shared__ float sMu[64], sRstd[64];
  int rt = blockIdx.x * 64;
  int colTile = blockIdx.y * 64;
  int tid = threadIdx.x;
  if (tid < 64){
    int row = rt + tid;
    int jb = row / NKEEP;
    int b = jb % BV;
    int tok = g_keep[row];
    sIdx[tid] = b*(NT+1) + 1 + tok;
    sMu[tid] = g_mu[row]; sRstd[tid] = g_rstd[row];
  }
  __syncthreads();
  float acc[4][4];
  #pragma unroll
  for (int i=0;i<4;i++)
    #pragma unroll
    for (int jj=0;jj<4;jj++) acc[i][jj] = 0.f;
  int ty = tid >> 4, tx = tid & 15;
  for (int kt = 0; kt < CD; kt += 32){
    #pragma unroll
    for (int i=0;i<8;i++){
      int f = i*256 + tid;
      int r = f >> 5, c = f & 31;
      float v = img[(size_t)sIdx[r]*CD + kt + c];
      As[c][r] = (v - sMu[r]) * sRstd[r] * __ldg(&lng[kt+c]) + __ldg(&lnb[kt+c]);
    }
    #pragma unroll
    for (int i=0;i<8;i++){
      int f = i*256 + tid;
      int kk = f >> 6, nn = f & 63;
      int col = colTile + nn;
      Bs[kk][nn] = (col < HIDN) ? w1[(size_t)(kt+kk)*HIDN + col] : 0.f;
    }
    __syncthreads();
    #pragma unroll
    for (int kk=0; kk<32; kk++){
      float4 a = *(const float4*)&As[kk][ty<<2];
      float4 bq = *(const float4*)&Bs[kk][tx<<2];
      float av[4] = {a.x,a.y,a.z,a.w};
      float bv[4] = {bq.x,bq.y,bq.z,bq.w};
      #pragma unroll
      for (int i=0;i<4;i++)
        #pragma unroll
        for (int jj=0;jj<4;jj++) acc[i][jj] += av[i]*bv[jj];
    }
    __syncthreads();
  }
  #pragma unroll
  for (int i=0;i<4;i++){
    int row = rt + (ty<<2) + i;
    #pragma unroll
    for (int jj=0;jj<4;jj++){
      int col = colTile + (tx<<2) + jj;
      if (col < HIDN){
        float x = acc[i][jj] + __ldg(&b1[col]);
        float gl = 0.5f * x * (1.0f + erff(x * 0.70710678118654752f));
        g_h[(size_t)row*HIDN + col] = gl;
      }
    }
  }
}

// ------------- GEMM2: logits = H @ w2 + b2, 225792 x 39 ---------------------
__global__ void k_mlp2(const float* __restrict__ w2, const float* __restrict__ b2){
  __shared__ float Hs[64*104];
  __shared__ float w2s[HIDN*40];
  __shared__ float b2s[NSEL];
  int rt = blockIdx.x * 64;
  int tid = threadIdx.x;
  for (int f = tid; f < 64*HIDN; f += 256){
    int r = f / HIDN, c = f - r*HIDN;
    Hs[r*104 + c] = g_h[(size_t)rt*HIDN + f];
  }
  for (int f = tid; f < HIDN*NSEL; f += 256){
    int h = f / NSEL, t = f - h*NSEL;
    w2s[h*40 + t] = w2[f];
  }
  if (tid < NSEL) b2s[tid] = b2[tid];
  __syncthreads();
  for (int o = tid; o < 64*NSEL; o += 256){
    int r = o / NSEL, t = o - r*NSEL;
    float acc = b2s[t];
    #pragma unroll 6
    for (int c=0;c<HIDN;c++) acc += Hs[r*104 + c] * w2s[c*40 + t];
    g_logits[(size_t)rt*NSEL + o] = acc;
  }
}

// ----------------------- fused finale per (j,b) -----------------------------
#define OFF_WT   0
#define OFF_TOKS 3904
#define OFF_C2T  25064
#define OFF_CAPC 26376
#define OFF_KEEP 30600
#define OFF_REDA 30698
#define OFF_REDB 30730
#define FINAL_SMEM (30772*4)
#define TOKS_STRIDE 516
__global__ void k_final(const float* __restrict__ img,
                        const float* __restrict__ scale,
                        float* __restrict__ out){
  extern __shared__ float sm[];
  float* wt   = sm + OFF_WT;      // [39][100]
  float* toks = sm + OFF_TOKS;    // [41][516]
  float* c2t  = sm + OFF_C2T;     // [32*41]
  float* capc = sm + OFF_CAPC;    // [32][132]
  int*   keeps= (int*)(sm + OFF_KEEP);
  float* redA = sm + OFF_REDA;
  float* redB = sm + OFF_REDB;
  int jb = blockIdx.x; int j = jb / BV, b = jb % BV;
  int tid = threadIdx.x;
  float sc = __ldg(scale);
  // load logits (transposed) * scale
  for (int f = tid; f < NKEEP*NSEL; f += 256){
    int k = f / NSEL, t = f - k*NSEL;
    wt[t*100 + k] = g_logits[(size_t)jb*NKEEP*NSEL + f] * sc;
  }
  if (tid < NKEEP) keeps[tid] = g_keep[(size_t)jb*NKEEP + tid];
  __syncthreads();
  // softmax over k per t
  if (tid < NSEL){
    int t = tid;
    float mx = -3.4e38f;
    for (int k=0;k<NKEEP;k++) mx = fmaxf(mx, wt[t*100+k]);
    float s = 0.f;
    for (int k=0;k<NKEEP;k++){ float e = expf(wt[t*100+k]-mx); wt[t*100+k]=e; s+=e; }
    float inv = 1.0f/s;
    for (int k=0;k<NKEEP;k++) wt[t*100+k] *= inv;
  }
  __syncthreads();
  // aggregation: toks rows 1..39
  for (int half = 0; half < 2; half++){
    int c = half*256 + tid;
    float acc[NSEL];
    #pragma unroll
    for (int t=0;t<NSEL;t++) acc[t] = 0.f;
    for (int k=0;k<NKEEP;k++){
      float sv = img[((size_t)(b*(NT+1) + 1 + keeps[k]))*CD + c];
      #pragma unroll
      for (int t=0;t<NSEL;t++) acc[t] += wt[t*100+k]*sv;
    }
    #pragma unroll
    for (int t=0;t<NSEL;t++) toks[(1+t)*TOKS_STRIDE + c] = acc[t];
  }
  // cls + extra rows
  for (int f = tid; f < CD; f += 256){
    toks[0*TOKS_STRIDE + f]  = img[((size_t)(b*(NT+1)))*CD + f];
    toks[40*TOKS_STRIDE + f] = g_extra[(size_t)jb*CD + f];
  }
  __syncthreads();
  // l2norm each of 41 token rows
  {
    int wid = tid >> 5, lane = tid & 31;
    for (int r = wid; r < NTOKS; r += 8){
      float4* p = (float4*)&toks[r*TOKS_STRIDE];
      float ss = 0.f;
      float4 vv[4];
      #pragma unroll
      for (int i=0;i<4;i++){
        vv[i] = p[lane + i*32];
        ss += vv[i].x*vv[i].x + vv[i].y*vv[i].y + vv[i].z*vv[i].z + vv[i].w*vv[i].w;
      }
      ss = warpSum(ss);
      float inv = 1.0f / fmaxf(sqrtf(ss), 1e-12f);
      #pragma unroll
      for (int i=0;i<4;i++){
        float4 o = make_float4(vv[i].x*inv, vv[i].y*inv, vv[i].z*inv, vv[i].w*inv);
        p[lane + i*32] = o;
      }
    }
  }
  __syncthreads();
  // c2t = capn[j] . toks^T, leaky relu, store in smem
  float acc6[6];
  #pragma unroll
  for (int it=0;it<6;it++) acc6[it] = 0.f;
  for (int cc = 0; cc < CD; cc += 128){
    __syncthreads();
    for (int f = tid; f < 32*128; f += 256){
      int m = f >> 7, c = f & 127;
      capc[m*132 + c] = g_capn[((size_t)(j*MW + m))*CD + cc + c];
    }
    __syncthreads();
    #pragma unroll
    for (int it=0; it<6; it++){
      int p = tid + it*256;
      if (p < MW*NTOKS){
        int m = p / NTOKS, t = p - m*NTOKS;
        const float4* cp = (const float4*)&capc[m*132];
        const float4* tp = (const float4*)&toks[t*TOKS_STRIDE + cc];
        float s = 0.f;
        #pragma unroll
        for (int i=0;i<32;i++){
          float4 a = cp[i]; float4 x = tp[i];
          s += a.x*x.x + a.y*x.y + a.z*x.z + a.w*x.w;
        }
        acc6[it] += s;
      }
    }
  }
  __syncthreads();
  #pragma unroll
  for (int it=0;it<6;it++){
    int p = tid + it*256;
    if (p < MW*NTOKS){
      float v = acc6[it];
      c2t[p] = (v >= 0.f) ? v : 0.1f*v;
    }
  }
  __syncthreads();
  // reductions
  if (tid < MW){
    float mx = -3.4e38f;
    for (int t=0;t<NTOKS;t++) mx = fmaxf(mx, c2t[tid*NTOKS + t]);
    redA[tid] = mx;
  }
  if (tid < NTOKS){
    float mx = -3.4e38f;
    for (int m=0;m<MW;m++) mx = fmaxf(mx, c2t[m*NTOKS + tid]);
    redB[tid] = mx;
  }
  __syncthreads();
  if (tid == 0){
    float row = 0.f; for (int m=0;m<MW;m++) row += redA[m];
    row *= (1.0f/MW);
    float col = 0.f; for (int t=0;t<NTOKS;t++) col += redB[t];
    col *= (1.0f/NTOKS);
    out[b*BT + j] = row + col;
  }
}

// ----------------------------- launcher --------------------------------------
extern "C" void kernel_launch(void* const* d_in, const int* in_sizes, int n_in,
                              void* d_out, int out_size){
  const float* img   = (const float*)d_in[0];
  const float* cap   = (const float*)d_in[1];
  // d_in[2] = cap_lens (unused; all == M)
  const float* lng   = (const float*)d_in[3];
  const float* lnb   = (const float*)d_in[4];
  const float* w1    = (const float*)d_in[5];
  const float* b1    = (const float*)d_in[6];
  const float* w2    = (const float*)d_in[7];
  const float* b2    = (const float*)d_in[8];
  const float* scale = (const float*)d_in[9];
  float* out = (float*)d_out;

  cudaFuncSetAttribute(k_score, cudaFuncAttributeMaxDynamicSharedMemorySize, SCORE_SMEM);
  cudaFuncSetAttribute(k_final, cudaFuncAttributeMaxDynamicSharedMemorySize, FINAL_SMEM);

  k_capnorm<<<BT*MW, 128>>>(cap);
  k_spnorm<<<BV*NT, 128>>>(img);
  k_glo<<<BV, 256>>>(img);
  k_sim<<<BV, 256>>>();
  k_score<<<NPAIR, 256, SCORE_SMEM>>>();
  k_sort<<<NPAIR, 256>>>(img);
  k_mlp1<<<dim3(RTOT/64, 2), 256>>>(img, lng, lnb, w1, b1);
  k_mlp2<<<RTOT/64, 256>>>(w2, b2);
  k_final<<<NPAIR, 256, FINAL_SMEM>>>(img, scale, out);
}

// round 3
// speedup vs baseline: 1.7472x; 1.7472x over previous
#include <cuda_runtime.h>
#include <math.h>

#define BV 48
#define BT 48
#define MW 32
#define NT 196
#define CD 512
#define HIDN 102
#define NKEEP 98
#define NSEL 39
#define NTOKS 41
#define NPAIR (BT*BV)
#define RTOT (NPAIR*NKEEP)

typedef unsigned long long ull;

// ---------------- scratch (device globals) ----------------------------------
__device__ float g_capn[BT*MW*CD];
__device__ float g_spn[BV*NT*CD];
__device__ float g_glo[BV*CD];
__device__ float g_sim[BV*NT];
__device__ float g_score[NPAIR*NT];
__device__ int   g_keep[NPAIR*NKEEP];
__device__ float g_extra[NPAIR*CD];
__device__ float g_mu[NPAIR*NKEEP];
__device__ float g_rstd[NPAIR*NKEEP];
__device__ float g_h[(size_t)RTOT*HIDN];
__device__ float g_logits[(size_t)RTOT*NSEL];
__device__ float g_toks[(size_t)NPAIR*NTOKS*CD];
__device__ float g_tninv[NPAIR*NTOKS];

__device__ __forceinline__ float warpSum(float v){
  #pragma unroll
  for (int o=16;o;o>>=1) v += __shfl_xor_sync(0xffffffffu, v, o);
  return v;
}
__device__ __forceinline__ ull pk2(float lo, float hi){
  ull r; asm("mov.b64 %0, {%1,%2};" : "=l"(r) : "f"(lo), "f"(hi)); return r;
}
__device__ __forceinline__ void upk2(ull v, float& lo, float& hi){
  asm("mov.b64 {%0,%1}, %2;" : "=f"(lo), "=f"(hi) : "l"(v));
}
__device__ __forceinline__ ull fma2(ull a, ull b, ull c){
  ull d; asm("fma.rn.f32x2 %0, %1, %2, %3;" : "=l"(d) : "l"(a), "l"(b), "l"(c)); return d;
}

// ------------------------- caption row l2norm -------------------------------
__global__ void k_capnorm(const float* __restrict__ cap){
  int row = blockIdx.x; int tid = threadIdx.x; // 128
  const float4* src = (const float4*)(cap + (size_t)row*CD);
  float4 v = src[tid];
  float ss = v.x*v.x + v.y*v.y + v.z*v.z + v.w*v.w;
  ss = warpSum(ss);
  __shared__ float rs[4]; __shared__ float s_inv;
  if ((tid&31)==0) rs[tid>>5] = ss;
  __syncthreads();
  if (tid==0){ float s = rs[0]+rs[1]+rs[2]+rs[3]; s_inv = 1.0f/fmaxf(sqrtf(s), 1e-12f); }
  __syncthreads();
  float inv = s_inv;
  ((float4*)(g_capn + (size_t)row*CD))[tid] = make_float4(v.x*inv, v.y*inv, v.z*inv, v.w*inv);
}

// ------------------------- spatial row l2norm -------------------------------
__global__ void k_spnorm(const float* __restrict__ img){
  int row = blockIdx.x; int b = row / NT, n = row % NT;
  int tid = threadIdx.x; // 128
  const float4* src = (const float4*)(img + ((size_t)(b*(NT+1) + 1 + n))*CD);
  float4 v = src[tid];
  float ss = v.x*v.x + v.y*v.y + v.z*v.z + v.w*v.w;
  ss = warpSum(ss);
  __shared__ float rs[4]; __shared__ float s_inv;
  if ((tid&31)==0) rs[tid>>5] = ss;
  __syncthreads();
  if (tid==0){ float s = rs[0]+rs[1]+rs[2]+rs[3]; s_inv = 1.0f/fmaxf(sqrtf(s), 1e-12f); }
  __syncthreads();
  float inv = s_inv;
  ((float4*)(g_spn + (size_t)row*CD))[tid] = make_float4(v.x*inv, v.y*inv, v.z*inv, v.w*inv);
}

// ------------------- glo = l2norm(mean over tokens) -------------------------
__global__ void k_glo(const float* __restrict__ img){
  int b = blockIdx.x; int tid = threadIdx.x; // 256
  float a0 = 0.f, a1 = 0.f;
  for (int n = 0; n < NT; n++){
    const float* r = img + ((size_t)(b*(NT+1) + 1 + n))*CD;
    a0 += r[tid]; a1 += r[tid+256];
  }
  a0 *= (1.0f/NT); a1 *= (1.0f/NT);
  float ss = a0*a0 + a1*a1;
  ss = warpSum(ss);
  __shared__ float rs[8]; __shared__ float s_inv;
  if ((tid&31)==0) rs[tid>>5] = ss;
  __syncthreads();
  if (tid==0){ float s=0.f; for (int i=0;i<8;i++) s += rs[i]; s_inv = 1.0f/fmaxf(sqrtf(s),1e-12f); }
  __syncthreads();
  float inv = s_inv;
  g_glo[b*CD + tid]       = a0*inv;
  g_glo[b*CD + tid + 256] = a1*inv;
}

// ------------------- s_im = dot(glo[b], spn[b,n]) ----------------------------
__global__ void k_sim(){
  int b = blockIdx.x; int tid = threadIdx.x;
  int wid = tid >> 5, lane = tid & 31;
  __shared__ float sg[CD];
  sg[tid] = g_glo[b*CD + tid]; sg[tid+256] = g_glo[b*CD + tid + 256];
  __syncthreads();
  const float4* g4 = (const float4*)sg;
  for (int n = wid; n < NT; n += 8){
    const float4* sp = (const float4*)(g_spn + ((size_t)(b*NT + n))*CD);
    float d = 0.f;
    #pragma unroll
    for (int i=0;i<4;i++){
      float4 a = sp[lane + i*32]; float4 c = g4[lane + i*32];
      d += a.x*c.x + a.y*c.y + a.z*c.z + a.w*c.w;
    }
    d = warpSum(d);
    if (lane==0) g_sim[b*NT + n] = d;
  }
}

// ---- score: per (j,b) 32x196 GEMM + max over captions, f32x2 micro-tile ----
__global__ void k_score(){
  __shared__ __align__(16) float As[32][33];    // [kk][caption row]
  __shared__ __align__(16) float Bs[32][198];   // [kk][token]
  __shared__ float red[8][196];
  int jb = blockIdx.x; int j = jb / BV, b = jb % BV;
  int tid = threadIdx.x;
  int ty = tid >> 5, tx = tid & 31;
  ull acc[4][4];
  #pragma unroll
  for (int m=0;m<4;m++)
    #pragma unroll
    for (int i=0;i<4;i++) acc[m][i] = 0ull;
  for (int kt = 0; kt < CD; kt += 32){
    {
      int r = tid >> 3, q = tid & 7;
      float4 v = *(const float4*)&g_capn[((size_t)(j*MW + r))*CD + kt + q*4];
      As[q*4+0][r]=v.x; As[q*4+1][r]=v.y; As[q*4+2][r]=v.z; As[q*4+3][r]=v.w;
    }
    for (int f = tid; f < NT*8; f += 256){
      int t = f >> 3, q = f & 7;
      float4 v = *(const float4*)&g_spn[((size_t)(b*NT + t))*CD + kt + q*4];
      Bs[q*4+0][t]=v.x; Bs[q*4+1][t]=v.y; Bs[q*4+2][t]=v.z; Bs[q*4+3][t]=v.w;
    }
    __syncthreads();
    #pragma unroll
    for (int kk=0; kk<32; kk++){
      ull A0 = pk2(As[kk][ty],    As[kk][ty]);
      ull A1 = pk2(As[kk][ty+8],  As[kk][ty+8]);
      ull A2 = pk2(As[kk][ty+16], As[kk][ty+16]);
      ull A3 = pk2(As[kk][ty+24], As[kk][ty+24]);
      const ull* brow = (const ull*)&Bs[kk][0];
      ull b0 = brow[tx], b1 = brow[tx+32], b2 = brow[tx+64];
      acc[0][0]=fma2(A0,b0,acc[0][0]); acc[1][0]=fma2(A1,b0,acc[1][0]);
      acc[2][0]=fma2(A2,b0,acc[2][0]); acc[3][0]=fma2(A3,b0,acc[3][0]);
      acc[0][1]=fma2(A0,b1,acc[0][1]); acc[1][1]=fma2(A1,b1,acc[1][1]);
      acc[2][1]=fma2(A2,b1,acc[2][1]); acc[3][1]=fma2(A3,b1,acc[3][1]);
      acc[0][2]=fma2(A0,b2,acc[0][2]); acc[1][2]=fma2(A1,b2,acc[1][2]);
      acc[2][2]=fma2(A2,b2,acc[2][2]); acc[3][2]=fma2(A3,b2,acc[3][2]);
      if (tx < 2){
        ull b3 = brow[tx+96];
        acc[0][3]=fma2(A0,b3,acc[0][3]); acc[1][3]=fma2(A1,b3,acc[1][3]);
        acc[2][3]=fma2(A2,b3,acc[2][3]); acc[3][3]=fma2(A3,b3,acc[3][3]);
      }
    }
    __syncthreads();
  }
  #pragma unroll
  for (int i=0;i<4;i++){
    if (i==3 && tx>=2) break;
    int p = tx + 32*i;
    float lm = -3.4e38f, hm = -3.4e38f;
    #pragma unroll
    for (int m=0;m<4;m++){
      float lo, hi; upk2(acc[m][i], lo, hi);
      lm = fmaxf(lm, lo); hm = fmaxf(hm, hi);
    }
    red[ty][2*p] = lm;
    if (2*p+1 < NT) red[ty][2*p+1] = hm;
  }
  __syncthreads();
  if (tid < NT){
    float mx = red[0][tid];
    #pragma unroll
    for (int y=1;y<8;y++) mx = fmaxf(mx, red[y][tid]);
    g_score[(size_t)jb*NT + tid] = g_sim[b*NT + tid] + mx;
  }
}

// ---- per (j,b): bitonic sort, keep idx, extra token, LN stats ---------------
__global__ void k_sort(const float* __restrict__ img){
  __shared__ float vals[256];
  __shared__ int   idxs[256];
  __shared__ float wbuf[NKEEP];
  __shared__ float rs[8]; __shared__ float s_tot;
  int jb = blockIdx.x; int b = jb % BV;
  int tid = threadIdx.x;
  vals[tid] = (tid < NT) ? -g_score[(size_t)jb*NT + tid] : 3.4e38f;
  idxs[tid] = tid;
  __syncthreads();
  for (int k = 2; k <= 256; k <<= 1){
    for (int s = k >> 1; s > 0; s >>= 1){
      int ixj = tid ^ s;
      if (ixj > tid){
        bool up = ((tid & k) == 0);
        float v1 = vals[tid], v2 = vals[ixj];
        if ((v1 > v2) == up){
          vals[tid] = v2; vals[ixj] = v1;
          int t = idxs[tid]; idxs[tid] = idxs[ixj]; idxs[ixj] = t;
        }
      }
      __syncthreads();
    }
  }
  if (tid < NKEEP) g_keep[(size_t)jb*NKEEP + tid] = idxs[tid];
  float e = 0.f;
  if (tid < NKEEP){ e = expf(vals[NKEEP] - vals[NKEEP + tid]); wbuf[tid] = e; }
  float v = warpSum(e);
  if ((tid&31)==0) rs[tid>>5] = v;
  __syncthreads();
  if (tid==0){ float s=0.f; for (int i=0;i<8;i++) s += rs[i]; s_tot = s; }
  __syncthreads();
  float inv = 1.0f / s_tot;
  {
    float a0 = 0.f, a1 = 0.f;
    for (int i = 0; i < NKEEP; i++){
      float w = wbuf[i];
      const float* r = img + ((size_t)(b*(NT+1) + 1 + idxs[NKEEP+i]))*CD;
      a0 += w * r[tid]; a1 += w * r[tid+256];
    }
    g_extra[(size_t)jb*CD + tid]       = a0*inv;
    g_extra[(size_t)jb*CD + tid + 256] = a1*inv;
  }
  int wid = tid >> 5, lane = tid & 31;
  for (int r = wid; r < NKEEP; r += 8){
    int tok = idxs[r];
    const float4* p = (const float4*)(img + ((size_t)(b*(NT+1) + 1 + tok))*CD);
    float s = 0.f, ss = 0.f;
    #pragma unroll
    for (int i=0;i<4;i++){
      float4 x = p[lane + i*32];
      s  += x.x + x.y + x.z + x.w;
      ss += x.x*x.x + x.y*x.y + x.z*x.z + x.w*x.w;
    }
    s = warpSum(s); ss = warpSum(ss);
    if (lane==0){
      float mu = s * (1.0f/CD);
      float var = ss * (1.0f/CD) - mu*mu;
      g_mu[(size_t)jb*NKEEP + r]   = mu;
      g_rstd[(size_t)jb*NKEEP + r] = rsqrtf(var + 1e-5f);
    }
  }
}

// -------- GEMM1: H = gelu( LN(gathered sel) @ w1 + b1 ) ---------------------
__global__ void k_mlp1(const float* __restrict__ img,
                       const float* __restrict__ lng, const float* __restrict__ lnb,
                       const float* __restrict__ w1,  const float* __restrict__ b1){
  __shared__ __align__(16) float As[32][68];
  __shared__ __align__(16) float Bs[32][68];
  __shared__ int   sIdx[64];
  __shared__ float sMu[64], sRstd[64];
  int rt = blockIdx.x * 64;
  int colTile = blockIdx.y * 64;
  int tid = threadIdx.x;
  if (tid < 64){
    int row = rt + tid;
    int jb = row / NKEEP;
    int b = jb % BV;
    int tok = g_keep[row];
    sIdx[tid] = b*(NT+1) + 1 + tok;
    sMu[tid] = g_mu[row]; sRstd[tid] = g_rstd[row];
  }
  __syncthreads();
  ull acc[4][2];
  #pragma unroll
  for (int i=0;i<4;i++){ acc[i][0]=0ull; acc[i][1]=0ull; }
  int ty = tid >> 4, tx = tid & 15;
  for (int kt = 0; kt < CD; kt += 32){
    #pragma unroll
    for (int i=0;i<8;i++){
      int f = i*256 + tid;
      int r = f >> 5, c = f & 31;
      float v = img[(size_t)sIdx[r]*CD + kt + c];
      As[c][r] = (v - sMu[r]) * sRstd[r] * __ldg(&lng[kt+c]) + __ldg(&lnb[kt+c]);
    }
    #pragma unroll
    for (int i=0;i<8;i++){
      int f = i*256 + tid;
      int kk = f >> 6, nn = f & 63;
      int col = colTile + nn;
      Bs[kk][nn] = (col < HIDN) ? w1[(size_t)(kt+kk)*HIDN + col] : 0.f;
    }
    __syncthreads();
    #pragma unroll
    for (int kk=0; kk<32; kk++){
      float4 a = *(const float4*)&As[kk][ty<<2];
      const ull* bp = (const ull*)&Bs[kk][tx<<2];
      ull B0 = bp[0], B1 = bp[1];
      ull A0 = pk2(a.x,a.x), A1 = pk2(a.y,a.y), A2 = pk2(a.z,a.z), A3 = pk2(a.w,a.w);
      acc[0][0]=fma2(A0,B0,acc[0][0]); acc[0][1]=fma2(A0,B1,acc[0][1]);
      acc[1][0]=fma2(A1,B0,acc[1][0]); acc[1][1]=fma2(A1,B1,acc[1][1]);
      acc[2][0]=fma2(A2,B0,acc[2][0]); acc[2][1]=fma2(A2,B1,acc[2][1]);
      acc[3][0]=fma2(A3,B0,acc[3][0]); acc[3][1]=fma2(A3,B1,acc[3][1]);
    }
    __syncthreads();
  }
  #pragma unroll
  for (int i=0;i<4;i++){
    int row = rt + (ty<<2) + i;
    #pragma unroll
    for (int h=0;h<2;h++){
      float lo, hi; upk2(acc[i][h], lo, hi);
      float vv[2] = {lo, hi};
      #pragma unroll
      for (int q=0;q<2;q++){
        int col = colTile + (tx<<2) + h*2 + q;
        if (col < HIDN){
          float x = vv[q] + __ldg(&b1[col]);
          float gl = 0.5f * x * (1.0f + erff(x * 0.70710678118654752f));
          g_h[(size_t)row*HIDN + col] = gl;
        }
      }
    }
  }
}

// ------------- GEMM2: logits = H @ w2 + b2 ----------------------------------
__global__ void k_mlp2(const float* __restrict__ w2, const float* __restrict__ b2){
  __shared__ float Hs[64][104];
  __shared__ __align__(16) float w2s[HIDN][40];
  int rt = blockIdx.x * 64;
  int tid = threadIdx.x;
  for (int f = tid; f < 64*HIDN; f += 256){
    int r = f / HIDN, c = f - r*HIDN;
    Hs[r][c] = g_h[(size_t)rt*HIDN + f];
  }
  for (int f = tid; f < HIDN*NSEL; f += 256){
    int h = f / NSEL, t = f - h*NSEL;
    w2s[h][t] = w2[f];
  }
  for (int f = tid; f < HIDN; f += 256) w2s[f][39] = 0.f;
  __syncthreads();
  int r = tid >> 2, g = tid & 3;
  ull acc[5] = {0ull,0ull,0ull,0ull,0ull};
  for (int c = 0; c < HIDN; c++){
    float h = Hs[r][c];
    ull H = pk2(h,h);
    const ull* wp = (const ull*)&w2s[c][0];
    #pragma unroll
    for (int u=0;u<5;u++) acc[u] = fma2(H, wp[g + 4*u], acc[u]);
  }
  #pragma unroll
  for (int u=0;u<5;u++){
    float lo, hi; upk2(acc[u], lo, hi);
    int t0 = 2*(g + 4*u);
    g_logits[(size_t)(rt + r)*NSEL + t0] = lo + __ldg(&b2[t0]);
    if (t0 + 1 < NSEL)
      g_logits[(size_t)(rt + r)*NSEL + t0 + 1] = hi + __ldg(&b2[t0+1]);
  }
}

// ------- per (j,b): transpose-softmax + aggregation -> raw toks -------------
__global__ void k_aggr(const float* __restrict__ img, const float* __restrict__ scale){
  __shared__ float wt[NSEL][100];
  __shared__ __align__(16) float wtt[NKEEP][40];
  __shared__ int keeps[NKEEP];
  int jb = blockIdx.x; int b = jb % BV;
  int tid = threadIdx.x;
  float sc = __ldg(scale);
  for (int f = tid; f < NKEEP*NSEL; f += 256){
    int k = f / NSEL, t = f - k*NSEL;
    wt[t][k] = g_logits[(size_t)jb*NKEEP*NSEL + f] * sc;
  }
  if (tid < NKEEP) keeps[tid] = g_keep[(size_t)jb*NKEEP + tid];
  __syncthreads();
  if (tid < NSEL){
    float mx = -3.4e38f;
    for (int k=0;k<NKEEP;k++) mx = fmaxf(mx, wt[tid][k]);
    float s = 0.f;
    for (int k=0;k<NKEEP;k++){ float e = expf(wt[tid][k]-mx); wt[tid][k]=e; s+=e; }
    float inv = 1.0f/s;
    for (int k=0;k<NKEEP;k++) wt[tid][k] *= inv;
  }
  __syncthreads();
  for (int f = tid; f < NKEEP*NSEL; f += 256){
    int k = f / NSEL, t = f - k*NSEL;
    wtt[k][t] = wt[t][k];
  }
  if (tid < NKEEP) wtt[tid][39] = 0.f;
  __syncthreads();
  #pragma unroll
  for (int half = 0; half < 2; half++){
    int c = half*256 + tid;
    ull acc[20];
    #pragma unroll
    for (int u=0;u<20;u++) acc[u] = 0ull;
    float s0 = img[((size_t)(b*(NT+1) + 1 + keeps[0]))*CD + c];
    float s1 = img[((size_t)(b*(NT+1) + 1 + keeps[1]))*CD + c];
    for (int k = 0; k < NKEEP; k++){
      ull S = pk2(s0, s0);
      s0 = s1;
      if (k + 2 < NKEEP) s1 = img[((size_t)(b*(NT+1) + 1 + keeps[k+2]))*CD + c];
      const ull* w = (const ull*)&wtt[k][0];
      #pragma unroll
      for (int u=0;u<20;u++) acc[u] = fma2(S, w[u], acc[u]);
    }
    #pragma unroll
    for (int u=0;u<20;u++){
      float lo, hi; upk2(acc[u], lo, hi);
      int t0 = 2*u;
      g_toks[((size_t)jb*NTOKS + 1 + t0)*CD + c] = lo;
      if (t0 + 1 < NSEL) g_toks[((size_t)jb*NTOKS + 1 + t0 + 1)*CD + c] = hi;
    }
  }
  for (int f = tid; f < CD; f += 256){
    g_toks[((size_t)jb*NTOKS + 0)*CD + f]  = img[((size_t)(b*(NT+1)))*CD + f];
    g_toks[((size_t)jb*NTOKS + 40)*CD + f] = g_extra[(size_t)jb*CD + f];
  }
}

// ---------------- per (j,b): token inverse l2 norms --------------------------
__global__ void k_toknorm(){
  int jb = blockIdx.x; int tid = threadIdx.x;
  int wid = tid >> 5, lane = tid & 31;
  for (int r = wid; r < NTOKS; r += 8){
    const float4* p = (const float4*)&g_toks[((size_t)jb*NTOKS + r)*CD];
    float ss = 0.f;
    #pragma unroll
    for (int i=0;i<4;i++){
      float4 x = p[lane + i*32];
      ss += x.x*x.x + x.y*x.y + x.z*x.z + x.w*x.w;
    }
    ss = warpSum(ss);
    if (lane==0) g_tninv[jb*NTOKS + r] = 1.0f / fmaxf(sqrtf(ss), 1e-12f);
  }
}

// ----- per (j,b): c2t GEMM (32x41x512) + leaky + row/col reductions ---------
__global__ void k_c2t(float* __restrict__ out){
  __shared__ __align__(16) float As[32][33];   // [kk][caption row]
  __shared__ __align__(16) float Bs[32][48];   // [kk][token]
  __shared__ float c2t[MW][48];
  __shared__ float inv[48];
  __shared__ float redA[MW], redB[NTOKS];
  int jb = blockIdx.x; int j = jb / BV, b = jb % BV;
  int tid = threadIdx.x;
  int ty = tid >> 5, tx = tid & 31;
  if (tid < NTOKS) inv[tid] = g_tninv[jb*NTOKS + tid];
  else if (tid < 48) inv[tid] = 0.f;
  ull acc[4] = {0ull,0ull,0ull,0ull};
  for (int kt = 0; kt < CD; kt += 32){
    {
      int r = tid >> 3, q = tid & 7;
      float4 v = *(const float4*)&g_capn[((size_t)(j*MW + r))*CD + kt + q*4];
      As[q*4+0][r]=v.x; As[q*4+1][r]=v.y; As[q*4+2][r]=v.z; As[q*4+3][r]=v.w;
    }
    if (tid < 32*7){
      int kk = tid / 7, c = 41 + tid % 7;
      Bs[kk][c] = 0.f;
    }
    __syncthreads();
    for (int f = tid; f < NTOKS*8; f += 256){
      int t = f >> 3, q = f & 7;
      float4 v = *(const float4*)&g_toks[((size_t)jb*NTOKS + t)*CD + kt + q*4];
      Bs[q*4+0][t]=v.x; Bs[q*4+1][t]=v.y; Bs[q*4+2][t]=v.z; Bs[q*4+3][t]=v.w;
    }
    __syncthreads();
    if (tx < 24){
      #pragma unroll
      for (int kk=0; kk<32; kk++){
        ull B = ((const ull*)&Bs[kk][0])[tx];
        ull A0 = pk2(As[kk][ty],    As[kk][ty]);
        ull A1 = pk2(As[kk][ty+8],  As[kk][ty+8]);
        ull A2 = pk2(As[kk][ty+16], As[kk][ty+16]);
        ull A3 = pk2(As[kk][ty+24], As[kk][ty+24]);
        acc[0]=fma2(A0,B,acc[0]); acc[1]=fma2(A1,B,acc[1]);
        acc[2]=fma2(A2,B,acc[2]); acc[3]=fma2(A3,B,acc[3]);
      }
    }
    __syncthreads();
  }
  if (tx < 24){
    #pragma unroll
    for (int m=0;m<4;m++){
      float lo, hi; upk2(acc[m], lo, hi);
      int row = ty + 8*m;
      float v0 = lo * inv[2*tx];
      float v1 = hi * inv[2*tx+1];
      c2t[row][2*tx]   = (v0 >= 0.f) ? v0 : 0.1f*v0;
      c2t[row][2*tx+1] = (v1 >= 0.f) ? v1 : 0.1f*v1;
    }
  }
  __syncthreads();
  if (tid < MW){
    float mx = -3.4e38f;
    for (int t=0;t<NTOKS;t++) mx = fmaxf(mx, c2t[tid][t]);
    redA[tid] = mx;
  }
  if (tid < NTOKS){
    float mx = -3.4e38f;
    for (int m=0;m<MW;m++) mx = fmaxf(mx, c2t[m][tid]);
    redB[tid] = mx;
  }
  __syncthreads();
  if (tid == 0){
    float row = 0.f; for (int m=0;m<MW;m++) row += redA[m];
    row *= (1.0f/MW);
    float col = 0.f; for (int t=0;t<NTOKS;t++) col += redB[t];
    col *= (1.0f/NTOKS);
    out[b*BT + j] = row + col;
  }
}

// ----------------------------- launcher --------------------------------------
extern "C" void kernel_launch(void* const* d_in, const int* in_sizes, int n_in,
                              void* d_out, int out_size){
  const float* img   = (const float*)d_in[0];
  const float* cap   = (const float*)d_in[1];
  const float* lng   = (const float*)d_in[3];
  const float* lnb   = (const float*)d_in[4];
  const float* w1    = (const float*)d_in[5];
  const float* b1    = (const float*)d_in[6];
  const float* w2    = (const float*)d_in[7];
  const float* b2    = (const float*)d_in[8];
  const float* scale = (const float*)d_in[9];
  float* out = (float*)d_out;

  k_capnorm<<<BT*MW, 128>>>(cap);
  k_spnorm<<<BV*NT, 128>>>(img);
  k_glo<<<BV, 256>>>(img);
  k_sim<<<BV, 256>>>();
  k_score<<<NPAIR, 256>>>();
  k_sort<<<NPAIR, 256>>>(img);
  k_mlp1<<<dim3(RTOT/64, 2), 256>>>(img, lng, lnb, w1, b1);
  k_mlp2<<<RTOT/64, 256>>>(w2, b2);
  k_aggr<<<NPAIR, 256>>>(img, scale);
  k_toknorm<<<NPAIR, 256>>>();
  k_c2t<<<NPAIR, 256>>>(out);
}